// round 5
// baseline (speedup 1.0000x reference)
#include <cuda_runtime.h>

#define NMAX   50000
#define EMAX   800000
#define EH     32
#define NET    3
#define CDIM   96      // NET*EH
#define ABDIM  192     // A(96) | B(96)

// ---- device scratch (static: no allocation allowed) ----
__device__ float g_AB[NMAX * ABDIM];        // per-node A|B precompute     38.4 MB
__device__ float g_accum[NMAX * CDIM];      // scatter accumulators        19.2 MB
__device__ float g_cnt[NMAX * NET];         // per (node, etype) counts
__device__ float g_Hmean[NMAX * CDIM];      // mailbox means               19.2 MB
__device__ float g_NO[NMAX * 256];          // node GEMM out (both types)  51.2 MB
__device__ float g_H[NMAX * 64];            // layer-0 node output         12.8 MB
__device__ float g_Wcat[128 * ABDIM];       // staged/reorganized weights  (24576 f)

// ---------------------------------------------------------------------------
// Weight staging: eW (NET, 2K, EH) -> g_Wcat[K][192] with cols [A(96)|B(96)]
// ---------------------------------------------------------------------------
__global__ void prep_edge_w(const float* __restrict__ eW, int K) {
    int idx = blockIdx.x * blockDim.x + threadIdx.x;
    int tot = K * ABDIM;
    if (idx >= tot) return;
    int k = idx / ABDIM, c = idx - k * ABDIM;
    int half = c / CDIM;              // 0 = A (src part), 1 = B (dst part)
    int rem  = c % CDIM;
    int t = rem / EH, j = rem % EH;
    g_Wcat[idx] = eW[(size_t)t * (2 * K * EH) + (size_t)(half * K + k) * EH + j];
}

// nW (2, 96, OUTD) -> g_Wcat[96][2*OUTD] with cols [type0 | type1]
__global__ void prep_node_w(const float* __restrict__ nW, int OUTD) {
    int nc = 2 * OUTD;
    int tot = CDIM * nc;
    int idx = blockIdx.x * blockDim.x + threadIdx.x;
    if (idx >= tot) return;
    int k = idx / nc, c = idx - k * nc;
    int t = c / OUTD, j = c % OUTD;
    g_Wcat[idx] = nW[(size_t)t * CDIM * OUTD + (size_t)k * OUTD + j];
}

// ---------------------------------------------------------------------------
// Register-tiled GEMM: out[n][NC] = X[n][K] @ g_Wcat[K][NC]
// 64-row tile per block, 256 threads, thread = 8 rows x NC/32 cols
// ---------------------------------------------------------------------------
template <int K, int NC>
__global__ __launch_bounds__(256) void gemm_kernel(const float* __restrict__ X,
                                                   float* __restrict__ out, int n) {
    __shared__ float Xs[64][32];
    __shared__ float Ws[32 * NC];
    const int tid  = threadIdx.x;
    const int lane = tid & 31;
    const int warp = tid >> 5;
    const int base = blockIdx.x * 64;
    const int r0   = warp * 8;
    constexpr int CB = NC / 32;

    float acc[8][CB];
#pragma unroll
    for (int i = 0; i < 8; i++)
#pragma unroll
        for (int j = 0; j < CB; j++) acc[i][j] = 0.f;

    for (int kc = 0; kc < K; kc += 32) {
        // X tile (coalesced; warp-row layout so compute reads are uniform)
#pragma unroll
        for (int i = 0; i < 8; i++) {
            int r = warp + i * 8;
            int row = base + r;
            Xs[r][lane] = (row < n) ? X[(size_t)row * K + kc + lane] : 0.f;
        }
        // W tile (linear copy)
#pragma unroll
        for (int i = 0; i < (32 * NC) / 256; i++) {
            int idx = tid + i * 256;
            Ws[idx] = g_Wcat[kc * NC + idx];
        }
        __syncthreads();
#pragma unroll
        for (int kk = 0; kk < 32; kk++) {
            float xv[8], wv[CB];
#pragma unroll
            for (int i = 0; i < 8; i++) xv[i] = Xs[r0 + i][kk];   // warp-uniform broadcast
#pragma unroll
            for (int j = 0; j < CB; j++) wv[j] = Ws[kk * NC + lane + 32 * j]; // conflict-free
#pragma unroll
            for (int i = 0; i < 8; i++)
#pragma unroll
                for (int j = 0; j < CB; j++)
                    acc[i][j] = fmaf(xv[i], wv[j], acc[i][j]);
        }
        __syncthreads();
    }
#pragma unroll
    for (int i = 0; i < 8; i++) {
        int row = base + r0 + i;
        if (row < n) {
#pragma unroll
            for (int j = 0; j < CB; j++)
                out[(size_t)row * NC + lane + 32 * j] = acc[i][j];
        }
    }
}

// ---------------------------------------------------------------------------
// Zero accumulators (required every replay: graph is re-executed)
// ---------------------------------------------------------------------------
__global__ void zero_kernel(int n) {
    int stride = gridDim.x * blockDim.x;
    int tid = blockIdx.x * blockDim.x + threadIdx.x;
    int tot4 = n * (CDIM / 4);
    float4 z = make_float4(0.f, 0.f, 0.f, 0.f);
    for (int i = tid; i < tot4; i += stride) ((float4*)g_accum)[i] = z;
    int totc = n * NET;
    for (int i = tid; i < totc; i += stride) g_cnt[i] = 0.f;
}

// ---------------------------------------------------------------------------
// Edge pass: 8 threads / edge, float4 lanes.
// m = relu(A[src,t] + B[dst,t] + bias[t]); red.v4 scatter into accum[dst].
// ---------------------------------------------------------------------------
__global__ __launch_bounds__(256) void edge_kernel(const int* __restrict__ ei,
                                                   const int* __restrict__ et,
                                                   const float* __restrict__ eb, int E) {
    int gid = blockIdx.x * blockDim.x + threadIdx.x;
    int e = gid >> 3;
    if (e >= E) return;
    int l = gid & 7;
    int src = ei[e], dst = ei[E + e], t = et[e];

    const float4 a  = *(const float4*)(g_AB + (size_t)src * ABDIM + t * EH + l * 4);
    const float4 b  = *(const float4*)(g_AB + (size_t)dst * ABDIM + CDIM + t * EH + l * 4);
    const float4 bi = *(const float4*)(eb + t * EH + l * 4);
    float4 m;
    m.x = fmaxf(a.x + b.x + bi.x, 0.f);
    m.y = fmaxf(a.y + b.y + bi.y, 0.f);
    m.z = fmaxf(a.z + b.z + bi.z, 0.f);
    m.w = fmaxf(a.w + b.w + bi.w, 0.f);

    float* p = g_accum + (size_t)dst * CDIM + t * EH + l * 4;
    asm volatile("red.global.add.v4.f32 [%0], {%1,%2,%3,%4};"
                 :: "l"(p), "f"(m.x), "f"(m.y), "f"(m.z), "f"(m.w) : "memory");
    if (l == 0) atomicAdd(g_cnt + (size_t)dst * NET + t, 1.0f);
}

// ---------------------------------------------------------------------------
// Mailbox mean: g_Hmean = g_accum / max(cnt, 1)
// ---------------------------------------------------------------------------
__global__ void mean_kernel(int n) {
    int stride = gridDim.x * blockDim.x;
    int tot = n * (CDIM / 4);   // 24 float4 per node, 8 per etype
    for (int i = blockIdx.x * blockDim.x + threadIdx.x; i < tot; i += stride) {
        int node = i / 24;
        int q = i - node * 24;
        int t = q >> 3;
        float inv = 1.0f / fmaxf(g_cnt[node * NET + t], 1.0f);
        float4 v = ((const float4*)g_accum)[i];
        v.x *= inv; v.y *= inv; v.z *= inv; v.w *= inv;
        ((float4*)g_Hmean)[i] = v;
    }
}

// ---------------------------------------------------------------------------
// Select node-type output + bias + relu
// ---------------------------------------------------------------------------
template <int OUTD>
__global__ void select_kernel(const float* __restrict__ nb, const int* __restrict__ nt,
                              float* __restrict__ out, int n) {
    int stride = gridDim.x * blockDim.x;
    int tot = n * OUTD;
    for (int i = blockIdx.x * blockDim.x + threadIdx.x; i < tot; i += stride) {
        int node = i / OUTD, c = i - node * OUTD;
        int t = nt[node];
        float v = g_NO[(size_t)node * (2 * OUTD) + t * OUTD + c] + nb[t * OUTD + c];
        out[i] = fmaxf(v, 0.f);
    }
}

// ---------------------------------------------------------------------------
extern "C" void kernel_launch(void* const* d_in, const int* in_sizes, int n_in,
                              void* d_out, int out_size) {
    const float* nf  = (const float*)d_in[0];
    const int*   ei  = (const int*)  d_in[1];
    const int*   et  = (const int*)  d_in[2];
    const int*   nt  = (const int*)  d_in[3];
    const float* eW0 = (const float*)d_in[4];
    const float* eb0 = (const float*)d_in[5];
    const float* nW0 = (const float*)d_in[6];
    const float* nb0 = (const float*)d_in[7];
    const float* eW1 = (const float*)d_in[8];
    const float* eb1 = (const float*)d_in[9];
    const float* nW1 = (const float*)d_in[10];
    const float* nb1 = (const float*)d_in[11];
    float* out = (float*)d_out;

    const int N = in_sizes[3];
    const int E = in_sizes[2];

    float *pAB, *pHmean, *pNO, *pH;
    cudaGetSymbolAddress((void**)&pAB, g_AB);
    cudaGetSymbolAddress((void**)&pHmean, g_Hmean);
    cudaGetSymbolAddress((void**)&pNO, g_NO);
    cudaGetSymbolAddress((void**)&pH, g_H);

    const int nb64 = (N + 63) / 64;            // GEMM tiles
    const int gEdge = (E * 8 + 255) / 256;     // edge pass
    const int gMisc = 148 * 8;                 // grid-stride kernels

    // ---------------- layer 0 (128 -> 64) ----------------
    prep_edge_w<<<(128 * ABDIM + 255) / 256, 256>>>(eW0, 128);
    gemm_kernel<128, 192><<<nb64, 256>>>(nf, pAB, N);
    zero_kernel<<<gMisc, 256>>>(N);
    edge_kernel<<<gEdge, 256>>>(ei, et, eb0, E);
    mean_kernel<<<gMisc, 256>>>(N);
    prep_node_w<<<(CDIM * 128 + 255) / 256, 256>>>(nW0, 64);
    gemm_kernel<96, 128><<<nb64, 256>>>(pHmean, pNO, N);
    select_kernel<64><<<gMisc, 256>>>(nb0, nt, pH, N);

    // ---------------- layer 1 (64 -> 128) ----------------
    prep_edge_w<<<(64 * ABDIM + 255) / 256, 256>>>(eW1, 64);
    gemm_kernel<64, 192><<<nb64, 256>>>(pH, pAB, N);
    zero_kernel<<<gMisc, 256>>>(N);
    edge_kernel<<<gEdge, 256>>>(ei, et, eb1, E);
    mean_kernel<<<gMisc, 256>>>(N);
    prep_node_w<<<(CDIM * 256 + 255) / 256, 256>>>(nW1, 128);
    gemm_kernel<96, 256><<<nb64, 256>>>(pHmean, pNO, N);
    select_kernel<128><<<gMisc, 256>>>(nb1, nt, out, N);
}